// round 12
// baseline (speedup 1.0000x reference)
#include <cuda_runtime.h>
#include <math.h>
#include <stdint.h>

// Problem constants
#define Bx  2
#define Tx  2048
#define Cx  1024
#define Hx  16
#define Dx  64
#define C3x 3072   // 3*C

// Scratch (device globals: allocation-free per harness rules)
static __device__ float g_qkv[(size_t)Bx * Tx * C3x];   // 48 MB
static __device__ float g_y  [(size_t)Bx * Tx * Cx];    // 32 MB

// ---------------------------------------------------------------------------
// fp32 SIMT GEMM, double-buffered smem + register prefetch + split-N
// microtile (byte-identical to the R11-passing kernel).
// ---------------------------------------------------------------------------
__device__ __forceinline__ void gemm_db(
    const float* __restrict__ A, int lda,
    const float* __restrict__ Bp, int ldb,
    float* __restrict__ Cc, int ldc,
    int K, int m0, int n0,
    const float* __restrict__ bias)
{
    __shared__ __align__(16) float As[2][8][132];
    __shared__ __align__(16) float Bs[2][8][128];

    const int tid = threadIdx.x;
    const int tx = tid & 15;
    const int ty = tid >> 4;
    const int ar = tid >> 1;
    const int ac = (tid & 1) << 2;
    const int br = tid >> 5;
    const int bc = (tid & 31) << 2;

    float acc[8][8];
#pragma unroll
    for (int i = 0; i < 8; i++)
#pragma unroll
        for (int j = 0; j < 8; j++) acc[i][j] = 0.0f;

    {
        float4 va = *reinterpret_cast<const float4*>(
            &A[(size_t)(m0 + ar) * lda + ac]);
        float4 vb = *reinterpret_cast<const float4*>(
            &Bp[(size_t)br * ldb + n0 + bc]);
        As[0][ac + 0][ar] = va.x; As[0][ac + 1][ar] = va.y;
        As[0][ac + 2][ar] = va.z; As[0][ac + 3][ar] = va.w;
        *reinterpret_cast<float4*>(&Bs[0][br][bc]) = vb;
    }
    __syncthreads();

    int buf = 0;
    for (int k0 = 8; k0 < K + 8; k0 += 8) {
        const bool pf = (k0 < K);
        float4 va, vb;
        if (pf) {
            va = *reinterpret_cast<const float4*>(
                &A[(size_t)(m0 + ar) * lda + k0 + ac]);
            vb = *reinterpret_cast<const float4*>(
                &Bp[(size_t)(k0 + br) * ldb + n0 + bc]);
        }

#pragma unroll
        for (int kk = 0; kk < 8; kk++) {
            float4 a0 = *reinterpret_cast<const float4*>(&As[buf][kk][ty * 8]);
            float4 a1 = *reinterpret_cast<const float4*>(&As[buf][kk][ty * 8 + 4]);
            float4 b0 = *reinterpret_cast<const float4*>(&Bs[buf][kk][tx * 4]);
            float4 b1 = *reinterpret_cast<const float4*>(&Bs[buf][kk][64 + tx * 4]);
            float a[8] = {a0.x, a0.y, a0.z, a0.w, a1.x, a1.y, a1.z, a1.w};
            float b[8] = {b0.x, b0.y, b0.z, b0.w, b1.x, b1.y, b1.z, b1.w};
#pragma unroll
            for (int i = 0; i < 8; i++)
#pragma unroll
                for (int j = 0; j < 8; j++)
                    acc[i][j] += a[i] * b[j];
        }

        if (pf) {
            int nb = buf ^ 1;
            As[nb][ac + 0][ar] = va.x; As[nb][ac + 1][ar] = va.y;
            As[nb][ac + 2][ar] = va.z; As[nb][ac + 3][ar] = va.w;
            *reinterpret_cast<float4*>(&Bs[nb][br][bc]) = vb;
            __syncthreads();
            buf = nb;
        }
    }

    const int c0 = n0 + tx * 4;
    const int c1 = n0 + 64 + tx * 4;
    float4 bb0 = *reinterpret_cast<const float4*>(&bias[c0]);
    float4 bb1 = *reinterpret_cast<const float4*>(&bias[c1]);
#pragma unroll
    for (int i = 0; i < 8; i++) {
        int gm = m0 + ty * 8 + i;
        float4 o0 = make_float4(acc[i][0] + bb0.x, acc[i][1] + bb0.y,
                                acc[i][2] + bb0.z, acc[i][3] + bb0.w);
        float4 o1 = make_float4(acc[i][4] + bb1.x, acc[i][5] + bb1.y,
                                acc[i][6] + bb1.z, acc[i][7] + bb1.w);
        *reinterpret_cast<float4*>(&Cc[(size_t)gm * ldc + c0]) = o0;
        *reinterpret_cast<float4*>(&Cc[(size_t)gm * ldc + c1]) = o1;
    }
}

__global__ void __launch_bounds__(256) k_qkv(
    const float* __restrict__ x, const float* __restrict__ w,
    const float* __restrict__ bias)
{
    gemm_db(x, Cx, w, C3x, g_qkv, C3x,
            Cx, blockIdx.y * 128, blockIdx.x * 128, bias);
}

__global__ void __launch_bounds__(256) k_proj(
    const float* __restrict__ w, const float* __restrict__ bias,
    float* __restrict__ out)
{
    gemm_db(g_y, Cx, w, Cx, out, Cx,
            Cx, blockIdx.y * 128, blockIdx.x * 128, bias);
}

// ---------------------------------------------------------------------------
// Fused causal flash attention, max-free streaming softmax, now with
// register prefetch of next K/V tile and 2 syncs/tile (was 3):
//   prefetch(t+1) -> S(t) -> sync -> store K(t+1); PV(t) -> sync -> store V(t+1)
// Single-buffered smem stays race-free: K store conflicts with nothing PV
// reads; V store's readers are beyond the next S-phase sync.
// ---------------------------------------------------------------------------
#define FBM 64
#define FBK 32

__global__ void __launch_bounds__(128) k_flash()
{
    const int z = blockIdx.y, b = z >> 4, h = z & 15;
    const int m0 = blockIdx.x * FBM;
    const float* Qg = g_qkv + (size_t)b * Tx * C3x + h * Dx;
    const float* Kg = Qg + Cx;
    const float* Vg = Qg + 2 * Cx;
    float* Yg = g_y + (size_t)b * Tx * Cx + h * Dx;

    __shared__ __align__(16) float Qs[Dx][FBM + 4];
    __shared__ __align__(16) float Ks[Dx][FBK + 4];
    __shared__ __align__(16) float Vs[FBK][Dx];
    __shared__ __align__(16) float Ss[FBM][FBK];

    const int tid = threadIdx.x;
    const int tx = tid & 15;
    const int ty = tid >> 4;
    const int c0 = tx * 2;
    const int rbase = ty * 8;

    // Per-thread K/V load coordinates (4 float4 each, fixed strides)
    const int lc = tid >> 4;            // tile row 0..7 (+8 per step)
    const int ld = (tid & 15) << 2;     // dim 0..60

    // Load Q tile transposed, fold in 1/sqrt(D)
    for (int idx = tid; idx < FBM * (Dx / 4); idx += 128) {
        int r = idx >> 4;
        int d4 = (idx & 15) << 2;
        float4 v = *reinterpret_cast<const float4*>(
            &Qg[(size_t)(m0 + r) * C3x + d4]);
        Qs[d4 + 0][r] = v.x * 0.125f;
        Qs[d4 + 1][r] = v.y * 0.125f;
        Qs[d4 + 2][r] = v.z * 0.125f;
        Qs[d4 + 3][r] = v.w * 0.125f;
    }

    // Prologue: load tile 0 into regs, store to smem
    float4 kr[4], vr[4];
#pragma unroll
    for (int i = 0; i < 4; i++) {
        int c = lc + i * 8;
        kr[i] = *reinterpret_cast<const float4*>(&Kg[(size_t)c * C3x + ld]);
        vr[i] = *reinterpret_cast<const float4*>(&Vg[(size_t)c * C3x + ld]);
    }
#pragma unroll
    for (int i = 0; i < 4; i++) {
        int c = lc + i * 8;
        Ks[ld + 0][c] = kr[i].x; Ks[ld + 1][c] = kr[i].y;
        Ks[ld + 2][c] = kr[i].z; Ks[ld + 3][c] = kr[i].w;
        *reinterpret_cast<float4*>(&Vs[c][ld]) = vr[i];
    }
    __syncthreads();

    float l_i[8];
    float4 acc[8];
#pragma unroll
    for (int i = 0; i < 8; i++) {
        l_i[i] = 0.0f;
        acc[i] = make_float4(0.f, 0.f, 0.f, 0.f);
    }

    const int nTiles = (m0 + FBM) / FBK;
    for (int t = 0; t < nTiles; t++) {
        const int j0 = t * FBK;
        const bool pf = (t + 1 < nTiles);

        // Prefetch next K/V tile into registers (latency overlapped with S)
        if (pf) {
            const int jn = j0 + FBK;
#pragma unroll
            for (int i = 0; i < 4; i++) {
                int c = jn + lc + i * 8;
                kr[i] = *reinterpret_cast<const float4*>(
                    &Kg[(size_t)c * C3x + ld]);
                vr[i] = *reinterpret_cast<const float4*>(
                    &Vg[(size_t)c * C3x + ld]);
            }
        }

        // S = Q @ K^T for this tile (2 cols per thread, 8 rows)
        float s0[8], s1[8];
#pragma unroll
        for (int i = 0; i < 8; i++) { s0[i] = 0.f; s1[i] = 0.f; }
#pragma unroll 8
        for (int k = 0; k < Dx; k++) {
            float b0 = Ks[k][c0], b1 = Ks[k][c0 + 1];
            float4 qa = *reinterpret_cast<const float4*>(&Qs[k][rbase]);
            float4 qb = *reinterpret_cast<const float4*>(&Qs[k][rbase + 4]);
            s0[0] += qa.x * b0; s1[0] += qa.x * b1;
            s0[1] += qa.y * b0; s1[1] += qa.y * b1;
            s0[2] += qa.z * b0; s1[2] += qa.z * b1;
            s0[3] += qa.w * b0; s1[3] += qa.w * b1;
            s0[4] += qb.x * b0; s1[4] += qb.x * b1;
            s0[5] += qb.y * b0; s1[5] += qb.y * b1;
            s0[6] += qb.z * b0; s1[6] += qb.z * b1;
            s0[7] += qb.w * b0; s1[7] += qb.w * b1;
        }

        // Max-free: p = exp(s) (0 above diagonal); accumulate l
#pragma unroll
        for (int i = 0; i < 8; i++) {
            int r = m0 + rbase + i;
            float p0 = (j0 + c0     <= r) ? __expf(s0[i]) : 0.0f;
            float p1 = (j0 + c0 + 1 <= r) ? __expf(s1[i]) : 0.0f;
            l_i[i] += p0 + p1;
            Ss[rbase + i][c0]     = p0;
            Ss[rbase + i][c0 + 1] = p1;
        }
        __syncthreads();   // S done everywhere: Ks free, Ss visible

        // Store next K tile (PV does not read Ks)
        if (pf) {
#pragma unroll
            for (int i = 0; i < 4; i++) {
                int c = lc + i * 8;
                Ks[ld + 0][c] = kr[i].x; Ks[ld + 1][c] = kr[i].y;
                Ks[ld + 2][c] = kr[i].z; Ks[ld + 3][c] = kr[i].w;
            }
        }

        // acc += P @ V  (4 dims per thread at d = tx*4)
#pragma unroll 4
        for (int c = 0; c < FBK; c++) {
            float4 v = *reinterpret_cast<const float4*>(&Vs[c][tx * 4]);
#pragma unroll
            for (int i = 0; i < 8; i++) {
                float p = Ss[rbase + i][c];
                acc[i].x += p * v.x; acc[i].y += p * v.y;
                acc[i].z += p * v.z; acc[i].w += p * v.w;
            }
        }
        __syncthreads();   // PV done everywhere: Vs free, K store visible

        // Store next V tile (readers are past the next S-phase sync)
        if (pf) {
#pragma unroll
            for (int i = 0; i < 4; i++) {
                int c = lc + i * 8;
                *reinterpret_cast<float4*>(&Vs[c][ld]) = vr[i];
            }
        }
    }

    // Epilogue: reduce l across the 16 row-mates, then Y = acc / l
#pragma unroll
    for (int i = 0; i < 8; i++) {
        float l = l_i[i];
#pragma unroll
        for (int off = 8; off > 0; off >>= 1)
            l += __shfl_xor_sync(0xffffffffu, l, off);
        float inv = 1.0f / l;
        int r = m0 + rbase + i;
        float4 o = make_float4(acc[i].x * inv, acc[i].y * inv,
                               acc[i].z * inv, acc[i].w * inv);
        *reinterpret_cast<float4*>(&Yg[(size_t)r * Cx + tx * 4]) = o;
    }
}

// ---------------------------------------------------------------------------
extern "C" void kernel_launch(void* const* d_in, const int* in_sizes, int n_in,
                              void* d_out, int out_size)
{
    const float* x      = (const float*)d_in[0];
    const float* w_qkv  = (const float*)d_in[1];
    const float* b_qkv  = (const float*)d_in[2];
    const float* w_proj = (const float*)d_in[3];
    const float* b_proj = (const float*)d_in[4];
    float* out = (float*)d_out;

    k_qkv  <<<dim3(C3x / 128, (Bx * Tx) / 128), 256>>>(x, w_qkv, b_qkv);
    k_flash<<<dim3(Tx / FBM, Bx * Hx), 128>>>();
    k_proj <<<dim3(Cx / 128, (Bx * Tx) / 128), 256>>>(w_proj, b_proj, out);
}

// round 13
// speedup vs baseline: 1.0025x; 1.0025x over previous
#include <cuda_runtime.h>
#include <math.h>
#include <stdint.h>

// Problem constants
#define Bx  2
#define Tx  2048
#define Cx  1024
#define Hx  16
#define Dx  64
#define C3x 3072   // 3*C

// Scratch (device globals: allocation-free per harness rules)
static __device__ float g_qkv[(size_t)Bx * Tx * C3x];   // 48 MB
static __device__ float g_y  [(size_t)Bx * Tx * Cx];    // 32 MB

// ---------------------------------------------------------------------------
// fp32 SIMT GEMM, double-buffered smem + register prefetch + split-N
// microtile (byte-identical to the R11-passing kernel).
// ---------------------------------------------------------------------------
__device__ __forceinline__ void gemm_db(
    const float* __restrict__ A, int lda,
    const float* __restrict__ Bp, int ldb,
    float* __restrict__ Cc, int ldc,
    int K, int m0, int n0,
    const float* __restrict__ bias)
{
    __shared__ __align__(16) float As[2][8][132];
    __shared__ __align__(16) float Bs[2][8][128];

    const int tid = threadIdx.x;
    const int tx = tid & 15;
    const int ty = tid >> 4;
    const int ar = tid >> 1;
    const int ac = (tid & 1) << 2;
    const int br = tid >> 5;
    const int bc = (tid & 31) << 2;

    float acc[8][8];
#pragma unroll
    for (int i = 0; i < 8; i++)
#pragma unroll
        for (int j = 0; j < 8; j++) acc[i][j] = 0.0f;

    {
        float4 va = *reinterpret_cast<const float4*>(
            &A[(size_t)(m0 + ar) * lda + ac]);
        float4 vb = *reinterpret_cast<const float4*>(
            &Bp[(size_t)br * ldb + n0 + bc]);
        As[0][ac + 0][ar] = va.x; As[0][ac + 1][ar] = va.y;
        As[0][ac + 2][ar] = va.z; As[0][ac + 3][ar] = va.w;
        *reinterpret_cast<float4*>(&Bs[0][br][bc]) = vb;
    }
    __syncthreads();

    int buf = 0;
    for (int k0 = 8; k0 < K + 8; k0 += 8) {
        const bool pf = (k0 < K);
        float4 va, vb;
        if (pf) {
            va = *reinterpret_cast<const float4*>(
                &A[(size_t)(m0 + ar) * lda + k0 + ac]);
            vb = *reinterpret_cast<const float4*>(
                &Bp[(size_t)(k0 + br) * ldb + n0 + bc]);
        }

#pragma unroll
        for (int kk = 0; kk < 8; kk++) {
            float4 a0 = *reinterpret_cast<const float4*>(&As[buf][kk][ty * 8]);
            float4 a1 = *reinterpret_cast<const float4*>(&As[buf][kk][ty * 8 + 4]);
            float4 b0 = *reinterpret_cast<const float4*>(&Bs[buf][kk][tx * 4]);
            float4 b1 = *reinterpret_cast<const float4*>(&Bs[buf][kk][64 + tx * 4]);
            float a[8] = {a0.x, a0.y, a0.z, a0.w, a1.x, a1.y, a1.z, a1.w};
            float b[8] = {b0.x, b0.y, b0.z, b0.w, b1.x, b1.y, b1.z, b1.w};
#pragma unroll
            for (int i = 0; i < 8; i++)
#pragma unroll
                for (int j = 0; j < 8; j++)
                    acc[i][j] += a[i] * b[j];
        }

        if (pf) {
            int nb = buf ^ 1;
            As[nb][ac + 0][ar] = va.x; As[nb][ac + 1][ar] = va.y;
            As[nb][ac + 2][ar] = va.z; As[nb][ac + 3][ar] = va.w;
            *reinterpret_cast<float4*>(&Bs[nb][br][bc]) = vb;
            __syncthreads();
            buf = nb;
        }
    }

    const int c0 = n0 + tx * 4;
    const int c1 = n0 + 64 + tx * 4;
    float4 bb0 = *reinterpret_cast<const float4*>(&bias[c0]);
    float4 bb1 = *reinterpret_cast<const float4*>(&bias[c1]);
#pragma unroll
    for (int i = 0; i < 8; i++) {
        int gm = m0 + ty * 8 + i;
        float4 o0 = make_float4(acc[i][0] + bb0.x, acc[i][1] + bb0.y,
                                acc[i][2] + bb0.z, acc[i][3] + bb0.w);
        float4 o1 = make_float4(acc[i][4] + bb1.x, acc[i][5] + bb1.y,
                                acc[i][6] + bb1.z, acc[i][7] + bb1.w);
        *reinterpret_cast<float4*>(&Cc[(size_t)gm * ldc + c0]) = o0;
        *reinterpret_cast<float4*>(&Cc[(size_t)gm * ldc + c1]) = o1;
    }
}

__global__ void __launch_bounds__(256) k_qkv(
    const float* __restrict__ x, const float* __restrict__ w,
    const float* __restrict__ bias)
{
    gemm_db(x, Cx, w, C3x, g_qkv, C3x,
            Cx, blockIdx.y * 128, blockIdx.x * 128, bias);
}

__global__ void __launch_bounds__(256) k_proj(
    const float* __restrict__ w, const float* __restrict__ bias,
    float* __restrict__ out)
{
    gemm_db(g_y, Cx, w, Cx, out, Cx,
            Cx, blockIdx.y * 128, blockIdx.x * 128, bias);
}

// ---------------------------------------------------------------------------
// Fused causal flash attention, max-free streaming softmax.
// R10-passing skeleton (no prefetch, 3 syncs/tile) + issue-mix fixes:
//   * Ks read as float2 (64 LDS/tile, was 128 scalar)
//   * Ss written as float2 (8 stores, was 16 scalar)
//   * PV: 4 V-rows cached in registers per group; Ss read as float4
//     broadcast (all tx-lanes same addr) -> Ss LDS 256 -> 64 per tile
// ---------------------------------------------------------------------------
#define FBM 64
#define FBK 32

__global__ void __launch_bounds__(128) k_flash()
{
    const int z = blockIdx.y, b = z >> 4, h = z & 15;
    const int m0 = blockIdx.x * FBM;
    const float* Qg = g_qkv + (size_t)b * Tx * C3x + h * Dx;
    const float* Kg = Qg + Cx;
    const float* Vg = Qg + 2 * Cx;
    float* Yg = g_y + (size_t)b * Tx * Cx + h * Dx;

    __shared__ __align__(16) float Qs[Dx][FBM + 4];
    __shared__ __align__(16) float Ks[Dx][FBK + 4];
    __shared__ __align__(16) float Vs[FBK][Dx];
    __shared__ __align__(16) float Ss[FBM][FBK];

    const int tid = threadIdx.x;
    const int tx = tid & 15;
    const int ty = tid >> 4;
    const int c0 = tx * 2;
    const int rbase = ty * 8;

    // Load Q tile transposed, fold in 1/sqrt(D)
    for (int idx = tid; idx < FBM * (Dx / 4); idx += 128) {
        int r = idx >> 4;
        int d4 = (idx & 15) << 2;
        float4 v = *reinterpret_cast<const float4*>(
            &Qg[(size_t)(m0 + r) * C3x + d4]);
        Qs[d4 + 0][r] = v.x * 0.125f;
        Qs[d4 + 1][r] = v.y * 0.125f;
        Qs[d4 + 2][r] = v.z * 0.125f;
        Qs[d4 + 3][r] = v.w * 0.125f;
    }

    float l_i[8];
    float4 acc[8];
#pragma unroll
    for (int i = 0; i < 8; i++) {
        l_i[i] = 0.0f;
        acc[i] = make_float4(0.f, 0.f, 0.f, 0.f);
    }

    for (int j0 = 0; j0 <= m0 + FBM - FBK; j0 += FBK) {
        __syncthreads();  // smem reuse fence (also covers Q load, 1st iter)

        // K tile transposed: Ks[d][c] = K[j0+c][d]
        for (int idx = tid; idx < FBK * (Dx / 4); idx += 128) {
            int c = idx >> 4;
            int d4 = (idx & 15) << 2;
            float4 v = *reinterpret_cast<const float4*>(
                &Kg[(size_t)(j0 + c) * C3x + d4]);
            Ks[d4 + 0][c] = v.x; Ks[d4 + 1][c] = v.y;
            Ks[d4 + 2][c] = v.z; Ks[d4 + 3][c] = v.w;
        }
        // V tile natural: Vs[c][d]
        for (int idx = tid; idx < FBK * (Dx / 4); idx += 128) {
            int c = idx >> 4;
            int d4 = (idx & 15) << 2;
            *reinterpret_cast<float4*>(&Vs[c][d4]) =
                *reinterpret_cast<const float4*>(
                    &Vg[(size_t)(j0 + c) * C3x + d4]);
        }
        __syncthreads();

        // S = Q @ K^T for this tile (2 cols per thread via float2, 8 rows)
        float s0[8], s1[8];
#pragma unroll
        for (int i = 0; i < 8; i++) { s0[i] = 0.f; s1[i] = 0.f; }
#pragma unroll 8
        for (int k = 0; k < Dx; k++) {
            float2 bk = *reinterpret_cast<const float2*>(&Ks[k][c0]);
            float4 qa = *reinterpret_cast<const float4*>(&Qs[k][rbase]);
            float4 qb = *reinterpret_cast<const float4*>(&Qs[k][rbase + 4]);
            s0[0] += qa.x * bk.x; s1[0] += qa.x * bk.y;
            s0[1] += qa.y * bk.x; s1[1] += qa.y * bk.y;
            s0[2] += qa.z * bk.x; s1[2] += qa.z * bk.y;
            s0[3] += qa.w * bk.x; s1[3] += qa.w * bk.y;
            s0[4] += qb.x * bk.x; s1[4] += qb.x * bk.y;
            s0[5] += qb.y * bk.x; s1[5] += qb.y * bk.y;
            s0[6] += qb.z * bk.x; s1[6] += qb.z * bk.y;
            s0[7] += qb.w * bk.x; s1[7] += qb.w * bk.y;
        }

        // Max-free: p = exp(s) (0 above diagonal); accumulate l; float2 store
#pragma unroll
        for (int i = 0; i < 8; i++) {
            int r = m0 + rbase + i;
            float2 pp;
            pp.x = (j0 + c0     <= r) ? __expf(s0[i]) : 0.0f;
            pp.y = (j0 + c0 + 1 <= r) ? __expf(s1[i]) : 0.0f;
            l_i[i] += pp.x + pp.y;
            *reinterpret_cast<float2*>(&Ss[rbase + i][c0]) = pp;
        }
        __syncthreads();

        // acc += P @ V: V rows cached 4-at-a-time, Ss read as float4 bcast
#pragma unroll
        for (int cg = 0; cg < FBK / 4; cg++) {
            float4 v0 = *reinterpret_cast<const float4*>(&Vs[cg * 4 + 0][tx * 4]);
            float4 v1 = *reinterpret_cast<const float4*>(&Vs[cg * 4 + 1][tx * 4]);
            float4 v2 = *reinterpret_cast<const float4*>(&Vs[cg * 4 + 2][tx * 4]);
            float4 v3 = *reinterpret_cast<const float4*>(&Vs[cg * 4 + 3][tx * 4]);
#pragma unroll
            for (int i = 0; i < 8; i++) {
                float4 p = *reinterpret_cast<const float4*>(
                    &Ss[rbase + i][cg * 4]);
                acc[i].x += p.x * v0.x + p.y * v1.x + p.z * v2.x + p.w * v3.x;
                acc[i].y += p.x * v0.y + p.y * v1.y + p.z * v2.y + p.w * v3.y;
                acc[i].z += p.x * v0.z + p.y * v1.z + p.z * v2.z + p.w * v3.z;
                acc[i].w += p.x * v0.w + p.y * v1.w + p.z * v2.w + p.w * v3.w;
            }
        }
    }

    // Epilogue: reduce l across the 16 row-mates, then Y = acc / l
#pragma unroll
    for (int i = 0; i < 8; i++) {
        float l = l_i[i];
#pragma unroll
        for (int off = 8; off > 0; off >>= 1)
            l += __shfl_xor_sync(0xffffffffu, l, off);
        float inv = 1.0f / l;
        int r = m0 + rbase + i;
        float4 o = make_float4(acc[i].x * inv, acc[i].y * inv,
                               acc[i].z * inv, acc[i].w * inv);
        *reinterpret_cast<float4*>(&Yg[(size_t)r * Cx + tx * 4]) = o;
    }
}

// ---------------------------------------------------------------------------
extern "C" void kernel_launch(void* const* d_in, const int* in_sizes, int n_in,
                              void* d_out, int out_size)
{
    const float* x      = (const float*)d_in[0];
    const float* w_qkv  = (const float*)d_in[1];
    const float* b_qkv  = (const float*)d_in[2];
    const float* w_proj = (const float*)d_in[3];
    const float* b_proj = (const float*)d_in[4];
    float* out = (float*)d_out;

    k_qkv  <<<dim3(C3x / 128, (Bx * Tx) / 128), 256>>>(x, w_qkv, b_qkv);
    k_flash<<<dim3(Tx / FBM, Bx * Hx), 128>>>();
    k_proj <<<dim3(Cx / 128, (Bx * Tx) / 128), 256>>>(w_proj, b_proj, out);
}